// round 3
// baseline (speedup 1.0000x reference)
#include <cuda_runtime.h>

// Problem constants
#define B_DIM 16384
#define S_DIM 512
#define NS    2048   // 4*S
#define KTOT  1024   // 2*S (x-half + recurrent-half)
#define BS    (B_DIM * S_DIM)  // 8388608

// Scratch for pre-activation z [B, 4S] (128 MiB). __device__ global: allowed.
__device__ float g_z[(size_t)B_DIM * NS];

// ---------------------------------------------------------------------------
// GEMM: z = X @ W + Hr @ R   (M=16384, N=2048, K=1024 split in two 512 halves)
// X  : [B, S]   row-major (layer input)
// Hr : [B, S]   row-major (recurrent input = prev_c[layer], per NNI swap)
// W  : [S, 4S]  row-major
// R  : [S, 4S]  row-major
// ---------------------------------------------------------------------------
#define BM 128
#define BN 128
#define BK 16
#define APAD 4   // smem pad to reduce transpose-store conflicts, keeps 16B align

__global__ __launch_bounds__(256) void lstm_gemm_kernel(
    const float* __restrict__ X,
    const float* __restrict__ Hr,
    const float* __restrict__ Wk,
    const float* __restrict__ Rk)
{
    __shared__ float As[BK][BM + APAD];  // transposed: As[k][m]
    __shared__ float Bs[BK][BN];

    const int tid = threadIdx.x;
    const int bm  = blockIdx.y * BM;
    const int bn  = blockIdx.x * BN;

    const int tx = tid & 15;   // 16 thread-cols
    const int ty = tid >> 4;   // 16 thread-rows

    float acc[8][8];
    #pragma unroll
    for (int i = 0; i < 8; i++)
        #pragma unroll
        for (int j = 0; j < 8; j++)
            acc[i][j] = 0.f;

    for (int k0 = 0; k0 < KTOT; k0 += BK) {
        const float* Ap;
        const float* Bp;
        int kl;
        if (k0 < S_DIM) { Ap = X;  Bp = Wk; kl = k0; }
        else            { Ap = Hr; Bp = Rk; kl = k0 - S_DIM; }

        // Load A tile (BM x BK) transposed, and B tile (BK x BN).
        // 512 float4's each; 2 per thread.
        #pragma unroll
        for (int t = 0; t < 2; t++) {
            int f4 = tid + t * 256;

            // A: row-major [B, S]; f4 -> (row, 4 consecutive k)
            int arow = f4 >> 2;
            int kq   = (f4 & 3) * 4;
            float4 av = *reinterpret_cast<const float4*>(
                &Ap[(size_t)(bm + arow) * S_DIM + kl + kq]);
            As[kq + 0][arow] = av.x;
            As[kq + 1][arow] = av.y;
            As[kq + 2][arow] = av.z;
            As[kq + 3][arow] = av.w;

            // B: row-major [S, 4S]; f4 -> (k, 4 consecutive n)
            int bk = f4 >> 5;
            int c4 = (f4 & 31) * 4;
            *reinterpret_cast<float4*>(&Bs[bk][c4]) =
                *reinterpret_cast<const float4*>(
                    &Bp[(size_t)(kl + bk) * NS + bn + c4]);
        }
        __syncthreads();

        #pragma unroll
        for (int kk = 0; kk < BK; kk++) {
            float a[8], b[8];
            *reinterpret_cast<float4*>(&a[0]) =
                *reinterpret_cast<const float4*>(&As[kk][ty * 8]);
            *reinterpret_cast<float4*>(&a[4]) =
                *reinterpret_cast<const float4*>(&As[kk][ty * 8 + 4]);
            *reinterpret_cast<float4*>(&b[0]) =
                *reinterpret_cast<const float4*>(&Bs[kk][tx * 8]);
            *reinterpret_cast<float4*>(&b[4]) =
                *reinterpret_cast<const float4*>(&Bs[kk][tx * 8 + 4]);
            #pragma unroll
            for (int i = 0; i < 8; i++)
                #pragma unroll
                for (int j = 0; j < 8; j++)
                    acc[i][j] = fmaf(a[i], b[j], acc[i][j]);
        }
        __syncthreads();
    }

    // Store to z scratch
    #pragma unroll
    for (int i = 0; i < 8; i++) {
        size_t row = (size_t)(bm + ty * 8 + i) * NS + bn + tx * 8;
        #pragma unroll
        for (int jq = 0; jq < 2; jq++) {
            float4 v;
            v.x = acc[i][jq * 4 + 0];
            v.y = acc[i][jq * 4 + 1];
            v.z = acc[i][jq * 4 + 2];
            v.w = acc[i][jq * 4 + 3];
            *reinterpret_cast<float4*>(&g_z[row + jq * 4]) = v;
        }
    }
}

// ---------------------------------------------------------------------------
// Elementwise LSTM cell: gates from z, c_tm1 = prev_h[layer] (NNI swap)
// ---------------------------------------------------------------------------
__device__ __forceinline__ float sigf(float x) {
    return 1.f / (1.f + expf(-x));
}

__global__ __launch_bounds__(256) void lstm_cell_kernel(
    const float* __restrict__ Ctm1,   // [B, S] = prev_h[layer]
    const float* __restrict__ bias,   // [4S]
    float* __restrict__ h_out,        // [B, S]
    float* __restrict__ c_out)        // [B, S]
{
    int idx = blockIdx.x * blockDim.x + threadIdx.x;   // over B*S/4
    if (idx >= BS / 4) return;
    int b = idx >> 7;           // S/4 = 128 quads per row
    int s = (idx & 127) * 4;

    const float* zr = g_z + (size_t)b * NS;
    float4 zi = *reinterpret_cast<const float4*>(&zr[s]);
    float4 zf = *reinterpret_cast<const float4*>(&zr[s + 512]);
    float4 zg = *reinterpret_cast<const float4*>(&zr[s + 1024]);
    float4 zo = *reinterpret_cast<const float4*>(&zr[s + 1536]);

    float4 bi = *reinterpret_cast<const float4*>(&bias[s]);
    float4 bf = *reinterpret_cast<const float4*>(&bias[s + 512]);
    float4 bg = *reinterpret_cast<const float4*>(&bias[s + 1024]);
    float4 bo = *reinterpret_cast<const float4*>(&bias[s + 1536]);

    float4 ct = *reinterpret_cast<const float4*>(&Ctm1[(size_t)b * S_DIM + s]);

    float4 c, h;
    {
        float cc = sigf(zf.x + bf.x) * ct.x + sigf(zi.x + bi.x) * tanhf(zg.x + bg.x);
        c.x = cc; h.x = sigf(zo.x + bo.x) * tanhf(cc);
    }
    {
        float cc = sigf(zf.y + bf.y) * ct.y + sigf(zi.y + bi.y) * tanhf(zg.y + bg.y);
        c.y = cc; h.y = sigf(zo.y + bo.y) * tanhf(cc);
    }
    {
        float cc = sigf(zf.z + bf.z) * ct.z + sigf(zi.z + bi.z) * tanhf(zg.z + bg.z);
        c.z = cc; h.z = sigf(zo.z + bo.z) * tanhf(cc);
    }
    {
        float cc = sigf(zf.w + bf.w) * ct.w + sigf(zi.w + bi.w) * tanhf(zg.w + bg.w);
        c.w = cc; h.w = sigf(zo.w + bo.w) * tanhf(cc);
    }

    size_t o = (size_t)b * S_DIM + s;
    *reinterpret_cast<float4*>(&h_out[o]) = h;
    *reinterpret_cast<float4*>(&c_out[o]) = c;
}

// ---------------------------------------------------------------------------
// Launch: 2 layers, sequential. Layer 2's x = layer 1's c (lives in d_out).
// ---------------------------------------------------------------------------
extern "C" void kernel_launch(void* const* d_in, const int* in_sizes, int n_in,
                              void* d_out, int out_size)
{
    const float* inputs  = (const float*)d_in[0];   // [B, S]
    const float* prev_c  = (const float*)d_in[1];   // [L, B, S]
    const float* prev_h  = (const float*)d_in[2];   // [L, B, S]
    const float* kernels = (const float*)d_in[3];   // [L, S, 4S]
    const float* recks   = (const float*)d_in[4];   // [L, S, 4S]
    const float* biases  = (const float*)d_in[5];   // [L, 4S]
    float* out = (float*)d_out;                     // [L, 2, B, S]

    dim3 ggrid(NS / BN, B_DIM / BM);   // (16, 128)
    int cell_blocks = (BS / 4 + 255) / 256;

    // ---- Layer 0 ----
    lstm_gemm_kernel<<<ggrid, 256>>>(inputs, prev_c, kernels, recks);
    lstm_cell_kernel<<<cell_blocks, 256>>>(prev_h, biases,
                                           out + 0 * (size_t)BS,   // h0
                                           out + 1 * (size_t)BS);  // c0
    // ---- Layer 1 ----  x = c0
    lstm_gemm_kernel<<<ggrid, 256>>>(out + 1 * (size_t)BS,
                                     prev_c + (size_t)BS,
                                     kernels + (size_t)S_DIM * NS,
                                     recks + (size_t)S_DIM * NS);
    lstm_cell_kernel<<<cell_blocks, 256>>>(prev_h + (size_t)BS,
                                           biases + NS,
                                           out + 2 * (size_t)BS,   // h1
                                           out + 3 * (size_t)BS);  // c1
}

// round 9
// speedup vs baseline: 2.8524x; 2.8524x over previous
#include <cuda_runtime.h>
#include <cuda_bf16.h>
#include <cstdint>

// Problem constants
#define B_DIM 16384
#define S_DIM 512
#define NS    2048   // 4*S
#define KTOT  1024   // 2*S (x-half + recurrent-half)
#define BS    (B_DIM * S_DIM)  // 8388608

// ---------------------------------------------------------------------------
// Device scratch (static __device__: allocation-guard safe)
// ---------------------------------------------------------------------------
__device__ float g_z[(size_t)B_DIM * NS];                       // 128 MiB
__device__ __nv_bfloat16 g_Ah[(size_t)B_DIM * KTOT];            // 32 MiB
__device__ __nv_bfloat16 g_Al[(size_t)B_DIM * KTOT];            // 32 MiB
__device__ __nv_bfloat16 g_Bh[(size_t)2 * NS * KTOT];           // 8 MiB  (per-layer [N,K])
__device__ __nv_bfloat16 g_Bl[(size_t)2 * NS * KTOT];           // 8 MiB

// ---------------------------------------------------------------------------
// PTX helpers — sm_80+ features only (compute_103 virtual target safe)
// ---------------------------------------------------------------------------
__device__ __forceinline__ uint32_t smem_u32(const void* p) {
    uint32_t a;
    asm("{ .reg .u64 t; cvta.to.shared.u64 t, %1; cvt.u32.u64 %0, t; }"
        : "=r"(a) : "l"(p));
    return a;
}

#define CP_ASYNC16(dst_u32, src_ptr) \
    asm volatile("cp.async.cg.shared.global [%0], [%1], 16;" \
                 :: "r"((uint32_t)(dst_u32)), "l"((const void*)(src_ptr)) : "memory")
#define CP_COMMIT() asm volatile("cp.async.commit_group;" ::: "memory")
#define CP_WAIT1()  asm volatile("cp.async.wait_group 1;" ::: "memory")
#define CP_WAIT0()  asm volatile("cp.async.wait_group 0;" ::: "memory")

// SW128 swizzle on byte offset within a 1024-aligned tile (128B rows)
#define SWZ(o) ((o) ^ (((o) >> 3) & 0x70))

#define LDSM_X4(r, addr) \
    asm volatile("ldmatrix.sync.aligned.m8n8.x4.shared.b16 {%0,%1,%2,%3}, [%4];" \
                 : "=r"((r)[0]), "=r"((r)[1]), "=r"((r)[2]), "=r"((r)[3]) \
                 : "r"((uint32_t)(addr)))

#define MMA16816(d, a, b0, b1) \
    asm volatile("mma.sync.aligned.m16n8k16.row.col.f32.bf16.bf16.f32 " \
                 "{%0,%1,%2,%3}, {%4,%5,%6,%7}, {%8,%9}, {%0,%1,%2,%3};" \
                 : "+f"((d)[0]), "+f"((d)[1]), "+f"((d)[2]), "+f"((d)[3]) \
                 : "r"((a)[0]), "r"((a)[1]), "r"((a)[2]), "r"((a)[3]), \
                   "r"(b0), "r"(b1))

// ---------------------------------------------------------------------------
// Conversion kernels
// ---------------------------------------------------------------------------
__device__ __forceinline__ void split4_store(float4 v, __nv_bfloat16* ph, __nv_bfloat16* pl) {
    __nv_bfloat16 h0 = __float2bfloat16_rn(v.x);
    __nv_bfloat16 h1 = __float2bfloat16_rn(v.y);
    __nv_bfloat16 h2 = __float2bfloat16_rn(v.z);
    __nv_bfloat16 h3 = __float2bfloat16_rn(v.w);
    __nv_bfloat16 l0 = __float2bfloat16_rn(v.x - __bfloat162float(h0));
    __nv_bfloat16 l1 = __float2bfloat16_rn(v.y - __bfloat162float(h1));
    __nv_bfloat16 l2 = __float2bfloat16_rn(v.z - __bfloat162float(h2));
    __nv_bfloat16 l3 = __float2bfloat16_rn(v.w - __bfloat162float(h3));
    __nv_bfloat162 H0 = __halves2bfloat162(h0, h1);
    __nv_bfloat162 H1 = __halves2bfloat162(h2, h3);
    __nv_bfloat162 L0 = __halves2bfloat162(l0, l1);
    __nv_bfloat162 L1 = __halves2bfloat162(l2, l3);
    uint2 uh = make_uint2(*reinterpret_cast<uint32_t*>(&H0), *reinterpret_cast<uint32_t*>(&H1));
    uint2 ul = make_uint2(*reinterpret_cast<uint32_t*>(&L0), *reinterpret_cast<uint32_t*>(&L1));
    *reinterpret_cast<uint2*>(ph) = uh;
    *reinterpret_cast<uint2*>(pl) = ul;
}

// A = [x | prev_c]  ->  g_Ah/g_Al [B, 1024]
__global__ __launch_bounds__(256) void convA_kernel(const float* __restrict__ X,
                                                    const float* __restrict__ Hr) {
    int i = blockIdx.x * 256 + threadIdx.x;   // over BS/4 (exact)
    int b = i >> 7;
    int s = (i & 127) * 4;
    float4 xv = *reinterpret_cast<const float4*>(&X[(size_t)b * S_DIM + s]);
    float4 hv = *reinterpret_cast<const float4*>(&Hr[(size_t)b * S_DIM + s]);
    size_t o = (size_t)b * KTOT + s;
    split4_store(xv, &g_Ah[o],         &g_Al[o]);
    split4_store(hv, &g_Ah[o + S_DIM], &g_Al[o + S_DIM]);
}

// B_t[n, k] = (k<512 ? W[k][n] : R[k-512][n])  ->  g_Bh/g_Bl  [N=2048, K=1024]
__global__ __launch_bounds__(256) void convB_kernel(const float* __restrict__ Wk,
                                                    const float* __restrict__ Rk,
                                                    size_t outOff) {
    __shared__ float t[32][33];
    int tx = threadIdx.x & 31, ty = threadIdx.x >> 5;   // 32x8
    int k0 = blockIdx.x * 32, n0 = blockIdx.y * 32;
    #pragma unroll
    for (int r = ty; r < 32; r += 8) {
        int kk = k0 + r;
        float v = (kk < S_DIM) ? Wk[(size_t)kk * NS + n0 + tx]
                               : Rk[(size_t)(kk - S_DIM) * NS + n0 + tx];
        t[r][tx] = v;
    }
    __syncthreads();
    #pragma unroll
    for (int r = ty; r < 32; r += 8) {
        int n = n0 + r;
        float v = t[tx][r];
        __nv_bfloat16 hi = __float2bfloat16_rn(v);
        __nv_bfloat16 lo = __float2bfloat16_rn(v - __bfloat162float(hi));
        size_t o = outOff + (size_t)n * KTOT + k0 + tx;
        g_Bh[o] = hi;
        g_Bl[o] = lo;
    }
}

// ---------------------------------------------------------------------------
// mma.sync GEMM: g_z[16384, 2048] = A[16384,1024] * B_t[2048,1024]^T
// bf16-split: AhBh + AlBh + AhBl, fp32 accumulate in registers.
// CTA tile 128x128, K chunks of 64, double-buffered cp.async stages (SW128).
// Warps: 4x2 grid -> warp tile 32(m) x 64(n); m16n8k16 HMMA.
// ---------------------------------------------------------------------------
#define KC 64
#define NCHUNK (KTOT / KC)          // 16
#define TILE_B 16384                // 128 rows x 128 bytes
#define STAGE_B (4 * TILE_B)        // Ah, Al, Bh, Bl = 64 KB
#define SMEM_GEMM (2 * STAGE_B)     // 128 KB

#define OFF_AH 0
#define OFF_AL 16384
#define OFF_BH 32768
#define OFF_BL 49152

__device__ __forceinline__ void gemm_load_stage(uint32_t stage, int c, int bm, int bn, int tid,
                                                const __nv_bfloat16* __restrict__ Bh,
                                                const __nv_bfloat16* __restrict__ Bl) {
    const int kc = c * KC;
    #pragma unroll
    for (int i = 0; i < 4; i++) {
        int idx = tid + (i << 8);          // 0..1023
        int row = idx >> 3;
        int c16 = idx & 7;
        uint32_t so = SWZ((uint32_t)(row * 128 + c16 * 16));
        size_t ga = (size_t)(bm + row) * KTOT + kc + c16 * 8;
        size_t gb = (size_t)(bn + row) * KTOT + kc + c16 * 8;
        CP_ASYNC16(stage + OFF_AH + so, g_Ah + ga);
        CP_ASYNC16(stage + OFF_AL + so, g_Al + ga);
        CP_ASYNC16(stage + OFF_BH + so, Bh + gb);
        CP_ASYNC16(stage + OFF_BL + so, Bl + gb);
    }
}

__global__ __launch_bounds__(256) void lstm_gemm_mma(size_t bOff) {
    extern __shared__ char smem[];
    const uint32_t sb = smem_u32(smem);
    const int tid = threadIdx.x;
    const int wid = tid >> 5, lid = tid & 31;
    const int bm = blockIdx.y * 128;
    const int bn = blockIdx.x * 128;

    const __nv_bfloat16* Bh = g_Bh + bOff;
    const __nv_bfloat16* Bl = g_Bl + bOff;

    const int wm = (wid >> 1) * 32;   // warp m-origin: 0,32,64,96
    const int wn = (wid & 1) * 64;    // warp n-origin: 0,64

    // ldmatrix per-lane row/col-byte (within tile), pre-swizzle
    const int a_row = lid & 15;             // lanes 0-15 rows m..m+15; 16-31 repeat
    const int a_kb  = (lid >> 4) * 16;      // k-half select
    const int b_row = ((lid >> 4) << 3) + (lid & 7);   // n-tile pair rows
    const int b_kb  = ((lid >> 3) & 1) * 16;

    float acc[2][8][4];
    #pragma unroll
    for (int mt = 0; mt < 2; mt++)
        #pragma unroll
        for (int nt = 0; nt < 8; nt++)
            #pragma unroll
            for (int q = 0; q < 4; q++) acc[mt][nt][q] = 0.f;

    gemm_load_stage(sb, 0, bm, bn, tid, Bh, Bl);
    CP_COMMIT();

    for (int c = 0; c < NCHUNK; c++) {
        const int s = c & 1;
        if (c + 1 < NCHUNK) {
            gemm_load_stage(sb + (s ^ 1) * STAGE_B, c + 1, bm, bn, tid, Bh, Bl);
            CP_COMMIT();
            CP_WAIT1();   // current stage's loads done
        } else {
            CP_WAIT0();
        }
        __syncthreads();

        const uint32_t st = sb + s * STAGE_B;
        #pragma unroll
        for (int kk = 0; kk < 4; kk++) {
            const uint32_t kbb = kk * 32;
            // A fragments (hi, lo) for 2 m-tiles
            uint32_t ah[2][4], al[2][4];
            #pragma unroll
            for (int mt = 0; mt < 2; mt++) {
                uint32_t o = SWZ((uint32_t)((wm + mt * 16 + a_row) * 128) + kbb + a_kb);
                LDSM_X4(ah[mt], st + OFF_AH + o);
                LDSM_X4(al[mt], st + OFF_AL + o);
            }
            // B fragments (hi, lo) for 4 n-tile pairs (8 n-tiles)
            uint32_t bh[4][4], bl[4][4];
            #pragma unroll
            for (int np = 0; np < 4; np++) {
                uint32_t o = SWZ((uint32_t)((wn + np * 16 + b_row) * 128) + kbb + b_kb);
                LDSM_X4(bh[np], st + OFF_BH + o);
                LDSM_X4(bl[np], st + OFF_BL + o);
            }
            // 48 HMMAs: hh + lh + hl for each (m-tile, n-tile)
            #pragma unroll
            for (int mt = 0; mt < 2; mt++)
                #pragma unroll
                for (int np = 0; np < 4; np++) {
                    MMA16816(acc[mt][np * 2],     ah[mt], bh[np][0], bh[np][1]);
                    MMA16816(acc[mt][np * 2],     al[mt], bh[np][0], bh[np][1]);
                    MMA16816(acc[mt][np * 2],     ah[mt], bl[np][0], bl[np][1]);
                    MMA16816(acc[mt][np * 2 + 1], ah[mt], bh[np][2], bh[np][3]);
                    MMA16816(acc[mt][np * 2 + 1], al[mt], bh[np][2], bh[np][3]);
                    MMA16816(acc[mt][np * 2 + 1], ah[mt], bl[np][2], bl[np][3]);
                }
        }
        __syncthreads();
    }

    // Epilogue: acc layout per mma: lane l -> rows (l>>2), (l>>2)+8; cols (l&3)*2, +1
    const int er = lid >> 2;
    const int ec = (lid & 3) * 2;
    #pragma unroll
    for (int mt = 0; mt < 2; mt++) {
        #pragma unroll
        for (int nt = 0; nt < 8; nt++) {
            size_t row = (size_t)(bm + wm + mt * 16 + er);
            int col = bn + wn + nt * 8 + ec;
            *reinterpret_cast<float2*>(&g_z[row * NS + col]) =
                make_float2(acc[mt][nt][0], acc[mt][nt][1]);
            *reinterpret_cast<float2*>(&g_z[(row + 8) * NS + col]) =
                make_float2(acc[mt][nt][2], acc[mt][nt][3]);
        }
    }
}

// ---------------------------------------------------------------------------
// Elementwise LSTM cell (DRAM-bound already)
// ---------------------------------------------------------------------------
__device__ __forceinline__ float sigf(float x) { return 1.f / (1.f + expf(-x)); }

__global__ __launch_bounds__(256) void lstm_cell_kernel(
    const float* __restrict__ Ctm1, const float* __restrict__ bias,
    float* __restrict__ h_out, float* __restrict__ c_out) {
    int idx = blockIdx.x * blockDim.x + threadIdx.x;
    if (idx >= BS / 4) return;
    int b = idx >> 7;
    int s = (idx & 127) * 4;

    const float* zr = g_z + (size_t)b * NS;
    float4 zi = *reinterpret_cast<const float4*>(&zr[s]);
    float4 zf = *reinterpret_cast<const float4*>(&zr[s + 512]);
    float4 zg = *reinterpret_cast<const float4*>(&zr[s + 1024]);
    float4 zo = *reinterpret_cast<const float4*>(&zr[s + 1536]);

    float4 bi = *reinterpret_cast<const float4*>(&bias[s]);
    float4 bf = *reinterpret_cast<const float4*>(&bias[s + 512]);
    float4 bg = *reinterpret_cast<const float4*>(&bias[s + 1024]);
    float4 bo = *reinterpret_cast<const float4*>(&bias[s + 1536]);

    float4 ct = *reinterpret_cast<const float4*>(&Ctm1[(size_t)b * S_DIM + s]);

    float4 c, h;
    { float cc = sigf(zf.x + bf.x) * ct.x + sigf(zi.x + bi.x) * tanhf(zg.x + bg.x);
      c.x = cc; h.x = sigf(zo.x + bo.x) * tanhf(cc); }
    { float cc = sigf(zf.y + bf.y) * ct.y + sigf(zi.y + bi.y) * tanhf(zg.y + bg.y);
      c.y = cc; h.y = sigf(zo.y + bo.y) * tanhf(cc); }
    { float cc = sigf(zf.z + bf.z) * ct.z + sigf(zi.z + bi.z) * tanhf(zg.z + bg.z);
      c.z = cc; h.z = sigf(zo.z + bo.z) * tanhf(cc); }
    { float cc = sigf(zf.w + bf.w) * ct.w + sigf(zi.w + bi.w) * tanhf(zg.w + bg.w);
      c.w = cc; h.w = sigf(zo.w + bo.w) * tanhf(cc); }

    size_t o = (size_t)b * S_DIM + s;
    *reinterpret_cast<float4*>(&h_out[o]) = h;
    *reinterpret_cast<float4*>(&c_out[o]) = c;
}

// ---------------------------------------------------------------------------
// Launch
// ---------------------------------------------------------------------------
extern "C" void kernel_launch(void* const* d_in, const int* in_sizes, int n_in,
                              void* d_out, int out_size) {
    const float* inputs  = (const float*)d_in[0];   // [B, S]
    const float* prev_c  = (const float*)d_in[1];   // [L, B, S]
    const float* prev_h  = (const float*)d_in[2];   // [L, B, S]
    const float* kernels = (const float*)d_in[3];   // [L, S, 4S]
    const float* recks   = (const float*)d_in[4];   // [L, S, 4S]
    const float* biases  = (const float*)d_in[5];   // [L, 4S]
    float* out = (float*)d_out;                     // [L, 2, B, S]

    cudaFuncSetAttribute(lstm_gemm_mma, cudaFuncAttributeMaxDynamicSharedMemorySize, SMEM_GEMM);

    dim3 gB(KTOT / 32, NS / 32);           // (32, 64)
    dim3 gG(NS / 128, B_DIM / 128);        // (16, 128)
    int convA_blocks = (BS / 4) / 256;     // 8192
    int cell_blocks  = (BS / 4 + 255) / 256;

    // Weight conversion (both layers)
    convB_kernel<<<gB, 256>>>(kernels, recks, (size_t)0);
    convB_kernel<<<gB, 256>>>(kernels + (size_t)S_DIM * NS, recks + (size_t)S_DIM * NS,
                              (size_t)NS * KTOT);

    // ---- Layer 0 ----
    convA_kernel<<<convA_blocks, 256>>>(inputs, prev_c);
    lstm_gemm_mma<<<gG, 256, SMEM_GEMM>>>((size_t)0);
    lstm_cell_kernel<<<cell_blocks, 256>>>(prev_h, biases,
                                           out + 0 * (size_t)BS,   // h0
                                           out + 1 * (size_t)BS);  // c0
    // ---- Layer 1 ---- x = c0
    convA_kernel<<<convA_blocks, 256>>>(out + 1 * (size_t)BS, prev_c + (size_t)BS);
    lstm_gemm_mma<<<gG, 256, SMEM_GEMM>>>((size_t)NS * KTOT);
    lstm_cell_kernel<<<cell_blocks, 256>>>(prev_h + (size_t)BS, biases + NS,
                                           out + 2 * (size_t)BS,   // h1
                                           out + 3 * (size_t)BS);  // c1
}

// round 11
// speedup vs baseline: 4.2346x; 1.4846x over previous
#include <cuda_runtime.h>
#include <cuda_fp16.h>
#include <cstdint>

// Problem constants
#define B_DIM 16384
#define S_DIM 512
#define NS    2048   // 4*S
#define KTOT  1024   // 2*S (x-half + recurrent-half)
#define BS    (B_DIM * S_DIM)  // 8388608

// ---------------------------------------------------------------------------
// Device scratch (static __device__: allocation-guard safe)
// ---------------------------------------------------------------------------
__device__ float g_z[(size_t)B_DIM * NS];                 // 128 MiB
__device__ __half g_Ah[(size_t)B_DIM * KTOT];             // 32 MiB
__device__ __half g_Al[(size_t)B_DIM * KTOT];             // 32 MiB
__device__ __half g_Bh[(size_t)2 * NS * KTOT];            // 8 MiB  (per-layer [N,K])

// ---------------------------------------------------------------------------
// PTX helpers — sm_80+ features only (compute_103 virtual target safe)
// ---------------------------------------------------------------------------
__device__ __forceinline__ uint32_t smem_u32(const void* p) {
    uint32_t a;
    asm("{ .reg .u64 t; cvta.to.shared.u64 t, %1; cvt.u32.u64 %0, t; }"
        : "=r"(a) : "l"(p));
    return a;
}

#define CP_ASYNC16(dst_u32, src_ptr) \
    asm volatile("cp.async.cg.shared.global [%0], [%1], 16;" \
                 :: "r"((uint32_t)(dst_u32)), "l"((const void*)(src_ptr)) : "memory")
#define CP_COMMIT() asm volatile("cp.async.commit_group;" ::: "memory")
#define CP_WAIT1()  asm volatile("cp.async.wait_group 1;" ::: "memory")
#define CP_WAIT0()  asm volatile("cp.async.wait_group 0;" ::: "memory")

// SW128 swizzle on byte offset within a 1024-aligned tile (128B rows)
#define SWZ(o) ((o) ^ (((o) >> 3) & 0x70))

#define LDSM_X4(r, addr) \
    asm volatile("ldmatrix.sync.aligned.m8n8.x4.shared.b16 {%0,%1,%2,%3}, [%4];" \
                 : "=r"((r)[0]), "=r"((r)[1]), "=r"((r)[2]), "=r"((r)[3]) \
                 : "r"((uint32_t)(addr)))

#define MMA16816(d, a, b0, b1) \
    asm volatile("mma.sync.aligned.m16n8k16.row.col.f32.f16.f16.f32 " \
                 "{%0,%1,%2,%3}, {%4,%5,%6,%7}, {%8,%9}, {%0,%1,%2,%3};" \
                 : "+f"((d)[0]), "+f"((d)[1]), "+f"((d)[2]), "+f"((d)[3]) \
                 : "r"((a)[0]), "r"((a)[1]), "r"((a)[2]), "r"((a)[3]), \
                   "r"(b0), "r"(b1))

// ---------------------------------------------------------------------------
// Conversion kernels (fp16 hi/lo split for A; fp16 truncation for B)
// ---------------------------------------------------------------------------
__device__ __forceinline__ void split4_store(float4 v, __half* ph, __half* pl) {
    __half h0 = __float2half_rn(v.x);
    __half h1 = __float2half_rn(v.y);
    __half h2 = __float2half_rn(v.z);
    __half h3 = __float2half_rn(v.w);
    __half l0 = __float2half_rn(v.x - __half2float(h0));
    __half l1 = __float2half_rn(v.y - __half2float(h1));
    __half l2 = __float2half_rn(v.z - __half2float(h2));
    __half l3 = __float2half_rn(v.w - __half2float(h3));
    __half2 H0 = __halves2half2(h0, h1);
    __half2 H1 = __halves2half2(h2, h3);
    __half2 L0 = __halves2half2(l0, l1);
    __half2 L1 = __halves2half2(l2, l3);
    uint2 uh = make_uint2(*reinterpret_cast<uint32_t*>(&H0), *reinterpret_cast<uint32_t*>(&H1));
    uint2 ul = make_uint2(*reinterpret_cast<uint32_t*>(&L0), *reinterpret_cast<uint32_t*>(&L1));
    *reinterpret_cast<uint2*>(ph) = uh;
    *reinterpret_cast<uint2*>(pl) = ul;
}

// A = [x | prev_c]  ->  g_Ah/g_Al [B, 1024]
__global__ __launch_bounds__(256) void convA_kernel(const float* __restrict__ X,
                                                    const float* __restrict__ Hr) {
    int i = blockIdx.x * 256 + threadIdx.x;   // over BS/4 (exact)
    int b = i >> 7;
    int s = (i & 127) * 4;
    float4 xv = *reinterpret_cast<const float4*>(&X[(size_t)b * S_DIM + s]);
    float4 hv = *reinterpret_cast<const float4*>(&Hr[(size_t)b * S_DIM + s]);
    size_t o = (size_t)b * KTOT + s;
    split4_store(xv, &g_Ah[o],         &g_Al[o]);
    split4_store(hv, &g_Ah[o + S_DIM], &g_Al[o + S_DIM]);
}

// B_t[n, k] = (k<512 ? W[k][n] : R[k-512][n])  ->  g_Bh  [N=2048, K=1024]
__global__ __launch_bounds__(256) void convB_kernel(const float* __restrict__ Wk,
                                                    const float* __restrict__ Rk,
                                                    size_t outOff) {
    __shared__ float t[32][33];
    int tx = threadIdx.x & 31, ty = threadIdx.x >> 5;   // 32x8
    int k0 = blockIdx.x * 32, n0 = blockIdx.y * 32;
    #pragma unroll
    for (int r = ty; r < 32; r += 8) {
        int kk = k0 + r;
        float v = (kk < S_DIM) ? Wk[(size_t)kk * NS + n0 + tx]
                               : Rk[(size_t)(kk - S_DIM) * NS + n0 + tx];
        t[r][tx] = v;
    }
    __syncthreads();
    #pragma unroll
    for (int r = ty; r < 32; r += 8) {
        int n = n0 + r;
        g_Bh[outOff + (size_t)n * KTOT + k0 + tx] = __float2half_rn(t[tx][r]);
    }
}

// ---------------------------------------------------------------------------
// mma.sync GEMM: g_z[16384, 2048] = A[16384,1024] * B_t[2048,1024]^T
// fp16-split, 2 products: (Ah + Al) * Bh, fp32 accumulate in registers.
// CTA tile 128x128, K chunks of 64, double-buffered cp.async stages (SW128).
// Warps: 4x2 grid -> warp tile 32(m) x 64(n); m16n8k16 HMMA. 2 CTAs/SM.
// ---------------------------------------------------------------------------
#define KC 64
#define NCHUNK (KTOT / KC)          // 16
#define TILE_B 16384                // 128 rows x 128 bytes
#define STAGE_B (3 * TILE_B)        // Ah, Al, Bh = 48 KB
#define SMEM_GEMM (2 * STAGE_B)     // 96 KB

#define OFF_AH 0
#define OFF_AL 16384
#define OFF_BH 32768

__device__ __forceinline__ void gemm_load_stage(uint32_t stage, int c, int bm, int bn, int tid,
                                                const __half* __restrict__ Bh) {
    const int kc = c * KC;
    #pragma unroll
    for (int i = 0; i < 4; i++) {
        int idx = tid + (i << 8);          // 0..1023
        int row = idx >> 3;
        int c16 = idx & 7;
        uint32_t so = SWZ((uint32_t)(row * 128 + c16 * 16));
        size_t ga = (size_t)(bm + row) * KTOT + kc + c16 * 8;
        size_t gb = (size_t)(bn + row) * KTOT + kc + c16 * 8;
        CP_ASYNC16(stage + OFF_AH + so, g_Ah + ga);
        CP_ASYNC16(stage + OFF_AL + so, g_Al + ga);
        CP_ASYNC16(stage + OFF_BH + so, Bh + gb);
    }
}

__global__ __launch_bounds__(256, 2) void lstm_gemm_mma(size_t bOff) {
    extern __shared__ char smem[];
    const uint32_t sb = smem_u32(smem);
    const int tid = threadIdx.x;
    const int wid = tid >> 5, lid = tid & 31;
    const int bm = blockIdx.y * 128;
    const int bn = blockIdx.x * 128;

    const __half* Bh = g_Bh + bOff;

    const int wm = (wid >> 1) * 32;   // warp m-origin: 0,32,64,96
    const int wn = (wid & 1) * 64;    // warp n-origin: 0,64

    // ldmatrix per-lane row/col-byte (within tile), pre-swizzle
    const int a_row = lid & 15;             // lanes 0-15 rows m..m+15; 16-31 repeat
    const int a_kb  = (lid >> 4) * 16;      // k-half select
    const int b_row = ((lid >> 4) << 3) + (lid & 7);   // n-tile pair rows
    const int b_kb  = ((lid >> 3) & 1) * 16;

    float acc[2][8][4];
    #pragma unroll
    for (int mt = 0; mt < 2; mt++)
        #pragma unroll
        for (int nt = 0; nt < 8; nt++)
            #pragma unroll
            for (int q = 0; q < 4; q++) acc[mt][nt][q] = 0.f;

    gemm_load_stage(sb, 0, bm, bn, tid, Bh);
    CP_COMMIT();

    for (int c = 0; c < NCHUNK; c++) {
        const int s = c & 1;
        if (c + 1 < NCHUNK) {
            gemm_load_stage(sb + (s ^ 1) * STAGE_B, c + 1, bm, bn, tid, Bh);
            CP_COMMIT();
            CP_WAIT1();   // current stage's loads done
        } else {
            CP_WAIT0();
        }
        __syncthreads();

        const uint32_t st = sb + s * STAGE_B;
        #pragma unroll
        for (int kk = 0; kk < 4; kk++) {
            const uint32_t kbb = kk * 32;
            // A fragments (hi, lo) for 2 m-tiles
            uint32_t ah[2][4], al[2][4];
            #pragma unroll
            for (int mt = 0; mt < 2; mt++) {
                uint32_t o = SWZ((uint32_t)((wm + mt * 16 + a_row) * 128) + kbb + a_kb);
                LDSM_X4(ah[mt], st + OFF_AH + o);
                LDSM_X4(al[mt], st + OFF_AL + o);
            }
            // B fragments (hi) for 4 n-tile pairs (8 n-tiles)
            uint32_t bh[4][4];
            #pragma unroll
            for (int np = 0; np < 4; np++) {
                uint32_t o = SWZ((uint32_t)((wn + np * 16 + b_row) * 128) + kbb + b_kb);
                LDSM_X4(bh[np], st + OFF_BH + o);
            }
            // 32 HMMAs: (hi + lo) * hi for each (m-tile, n-tile)
            #pragma unroll
            for (int mt = 0; mt < 2; mt++)
                #pragma unroll
                for (int np = 0; np < 4; np++) {
                    MMA16816(acc[mt][np * 2],     ah[mt], bh[np][0], bh[np][1]);
                    MMA16816(acc[mt][np * 2],     al[mt], bh[np][0], bh[np][1]);
                    MMA16816(acc[mt][np * 2 + 1], ah[mt], bh[np][2], bh[np][3]);
                    MMA16816(acc[mt][np * 2 + 1], al[mt], bh[np][2], bh[np][3]);
                }
        }
        __syncthreads();
    }

    // Epilogue: acc layout per mma: lane l -> rows (l>>2), (l>>2)+8; cols (l&3)*2, +1
    const int er = lid >> 2;
    const int ec = (lid & 3) * 2;
    #pragma unroll
    for (int mt = 0; mt < 2; mt++) {
        #pragma unroll
        for (int nt = 0; nt < 8; nt++) {
            size_t row = (size_t)(bm + wm + mt * 16 + er);
            int col = bn + wn + nt * 8 + ec;
            *reinterpret_cast<float2*>(&g_z[row * NS + col]) =
                make_float2(acc[mt][nt][0], acc[mt][nt][1]);
            *reinterpret_cast<float2*>(&g_z[(row + 8) * NS + col]) =
                make_float2(acc[mt][nt][2], acc[mt][nt][3]);
        }
    }
}

// ---------------------------------------------------------------------------
// Elementwise LSTM cell (DRAM-bound already)
// ---------------------------------------------------------------------------
__device__ __forceinline__ float sigf(float x) { return 1.f / (1.f + expf(-x)); }

__global__ __launch_bounds__(256) void lstm_cell_kernel(
    const float* __restrict__ Ctm1, const float* __restrict__ bias,
    float* __restrict__ h_out, float* __restrict__ c_out) {
    int idx = blockIdx.x * blockDim.x + threadIdx.x;
    if (idx >= BS / 4) return;
    int b = idx >> 7;
    int s = (idx & 127) * 4;

    const float* zr = g_z + (size_t)b * NS;
    float4 zi = *reinterpret_cast<const float4*>(&zr[s]);
    float4 zf = *reinterpret_cast<const float4*>(&zr[s + 512]);
    float4 zg = *reinterpret_cast<const float4*>(&zr[s + 1024]);
    float4 zo = *reinterpret_cast<const float4*>(&zr[s + 1536]);

    float4 bi = *reinterpret_cast<const float4*>(&bias[s]);
    float4 bf = *reinterpret_cast<const float4*>(&bias[s + 512]);
    float4 bg = *reinterpret_cast<const float4*>(&bias[s + 1024]);
    float4 bo = *reinterpret_cast<const float4*>(&bias[s + 1536]);

    float4 ct = *reinterpret_cast<const float4*>(&Ctm1[(size_t)b * S_DIM + s]);

    float4 c, h;
    { float cc = sigf(zf.x + bf.x) * ct.x + sigf(zi.x + bi.x) * tanhf(zg.x + bg.x);
      c.x = cc; h.x = sigf(zo.x + bo.x) * tanhf(cc); }
    { float cc = sigf(zf.y + bf.y) * ct.y + sigf(zi.y + bi.y) * tanhf(zg.y + bg.y);
      c.y = cc; h.y = sigf(zo.y + bo.y) * tanhf(cc); }
    { float cc = sigf(zf.z + bf.z) * ct.z + sigf(zi.z + bi.z) * tanhf(zg.z + bg.z);
      c.z = cc; h.z = sigf(zo.z + bo.z) * tanhf(cc); }
    { float cc = sigf(zf.w + bf.w) * ct.w + sigf(zi.w + bi.w) * tanhf(zg.w + bg.w);
      c.w = cc; h.w = sigf(zo.w + bo.w) * tanhf(cc); }

    size_t o = (size_t)b * S_DIM + s;
    *reinterpret_cast<float4*>(&h_out[o]) = h;
    *reinterpret_cast<float4*>(&c_out[o]) = c;
}

// ---------------------------------------------------------------------------
// Launch
// ---------------------------------------------------------------------------
extern "C" void kernel_launch(void* const* d_in, const int* in_sizes, int n_in,
                              void* d_out, int out_size) {
    const float* inputs  = (const float*)d_in[0];   // [B, S]
    const float* prev_c  = (const float*)d_in[1];   // [L, B, S]
    const float* prev_h  = (const float*)d_in[2];   // [L, B, S]
    const float* kernels = (const float*)d_in[3];   // [L, S, 4S]
    const float* recks   = (const float*)d_in[4];   // [L, S, 4S]
    const float* biases  = (const float*)d_in[5];   // [L, 4S]
    float* out = (float*)d_out;                     // [L, 2, B, S]

    cudaFuncSetAttribute(lstm_gemm_mma, cudaFuncAttributeMaxDynamicSharedMemorySize, SMEM_GEMM);

    dim3 gB(KTOT / 32, NS / 32);           // (32, 64)
    dim3 gG(NS / 128, B_DIM / 128);        // (16, 128)
    int convA_blocks = (BS / 4) / 256;     // 8192
    int cell_blocks  = (BS / 4 + 255) / 256;

    // Weight conversion (both layers)
    convB_kernel<<<gB, 256>>>(kernels, recks, (size_t)0);
    convB_kernel<<<gB, 256>>>(kernels + (size_t)S_DIM * NS, recks + (size_t)S_DIM * NS,
                              (size_t)NS * KTOT);

    // ---- Layer 0 ----
    convA_kernel<<<convA_blocks, 256>>>(inputs, prev_c);
    lstm_gemm_mma<<<gG, 256, SMEM_GEMM>>>((size_t)0);
    lstm_cell_kernel<<<cell_blocks, 256>>>(prev_h, biases,
                                           out + 0 * (size_t)BS,   // h0
                                           out + 1 * (size_t)BS);  // c0
    // ---- Layer 1 ---- x = c0
    convA_kernel<<<convA_blocks, 256>>>(out + 1 * (size_t)BS, prev_c + (size_t)BS);
    lstm_gemm_mma<<<gG, 256, SMEM_GEMM>>>((size_t)NS * KTOT);
    lstm_cell_kernel<<<cell_blocks, 256>>>(prev_h + (size_t)BS, biases + NS,
                                           out + 2 * (size_t)BS,   // h1
                                           out + 3 * (size_t)BS);  // c1
}